// round 6
// baseline (speedup 1.0000x reference)
#include <cuda_runtime.h>

#define NQ   32768
#define MA   8192
#define DIM  8
#define SEG  4
#define APS  (MA/SEG)        // 2048 anchors per segment
#define BLKA 64              // scoring block = 64 anchors
#define NBLK (MA/BLKA)       // 128 blocks total
#define NBLK_SEG (APS/BLKA)  // 32 blocks per segment
#define CAP  24              // max candidate blocks before fallback
#define FLT_INF __int_as_float(0x7f800000)

// scratch (device globals; no allocation allowed)
__device__ __align__(16) unsigned g_pk[MA * 8];   // tf32 pairs (k,k+4) per anchor
__device__ __align__(16) float    g_nrm[MA];      // exact fp32 ||a||^2
__device__ float    g_bmin[NBLK * NQ];            // coarse block-min per (block, query)
__device__ unsigned g_bmax[DIM];                  // per-dim max |anchor| bits (monotone)

__device__ __forceinline__ unsigned f2tf(float v) {
    unsigned r; asm("cvt.rna.tf32.f32 %0,%1;" : "=r"(r) : "f"(v)); return r;
}

// m16n8k8 tf32, fp32 accum, anchor norms folded via C
__device__ __forceinline__ void mma8(float d[4], const unsigned a[4],
                                     unsigned b0, unsigned b1, float c0, float c1) {
    asm("mma.sync.aligned.m16n8k8.row.col.f32.tf32.tf32.f32 "
        "{%0,%1,%2,%3},{%4,%5,%6,%7},{%8,%9},{%10,%11,%12,%13};"
        : "=f"(d[0]), "=f"(d[1]), "=f"(d[2]), "=f"(d[3])
        : "r"(a[0]), "r"(a[1]), "r"(a[2]), "r"(a[3]),
          "r"(b0), "r"(b1), "f"(c0), "f"(c1), "f"(c0), "f"(c1));
}

// ---------------------------------------------------------------------------
// 1) Prep: tf32-pack anchors (pairs k,k+4), exact norms, per-dim |a| max
// ---------------------------------------------------------------------------
__global__ void prep_kernel(const float* __restrict__ anchors) {
    int a = blockIdx.x * 256 + threadIdx.x;
    const float4* ap = (const float4*)(anchors + (size_t)a * DIM);
    float4 v0 = ap[0], v1 = ap[1];
    float nrm = v0.x * v0.x;
    nrm = fmaf(v0.y, v0.y, nrm); nrm = fmaf(v0.z, v0.z, nrm); nrm = fmaf(v0.w, v0.w, nrm);
    nrm = fmaf(v1.x, v1.x, nrm); nrm = fmaf(v1.y, v1.y, nrm); nrm = fmaf(v1.z, v1.z, nrm);
    nrm = fmaf(v1.w, v1.w, nrm);
    g_nrm[a] = nrm;
    unsigned* o = g_pk + a * 8;
    o[0] = f2tf(v0.x); o[1] = f2tf(v1.x);   // (k0,k4)
    o[2] = f2tf(v0.y); o[3] = f2tf(v1.y);   // (k1,k5)
    o[4] = f2tf(v0.z); o[5] = f2tf(v1.z);   // (k2,k6)
    o[6] = f2tf(v0.w); o[7] = f2tf(v1.w);   // (k3,k7)

    unsigned um[8] = { __float_as_uint(fabsf(v0.x)), __float_as_uint(fabsf(v0.y)),
                       __float_as_uint(fabsf(v0.z)), __float_as_uint(fabsf(v0.w)),
                       __float_as_uint(fabsf(v1.x)), __float_as_uint(fabsf(v1.y)),
                       __float_as_uint(fabsf(v1.z)), __float_as_uint(fabsf(v1.w)) };
    __shared__ unsigned sm[8];
    if (threadIdx.x < 8) sm[threadIdx.x] = 0;
    __syncthreads();
#pragma unroll
    for (int d = 0; d < 8; ++d) um[d] = __reduce_max_sync(0xffffffffu, um[d]);
    if ((threadIdx.x & 31) == 0)
#pragma unroll
        for (int d = 0; d < 8; ++d) atomicMax(&sm[d], um[d]);
    __syncthreads();
    if (threadIdx.x < 8) atomicMax(&g_bmax[threadIdx.x], sm[threadIdx.x]);
}

// ---------------------------------------------------------------------------
// 2) Coarse: tf32 MMA, B direct from L2-resident prepacked array (no smem,
//    no syncs). Block = 4 warps x 32 queries x 1 segment. Writes complete
//    per-(query, block) coarse mins.
// ---------------------------------------------------------------------------
__global__ void __launch_bounds__(128, 7)
coarse_kernel(const float* __restrict__ x) {
    int seg  = blockIdx.x & (SEG - 1);
    int qblk = blockIdx.x >> 2;
    int warp = threadIdx.x >> 5, lane = threadIdx.x & 31;
    int gid = lane >> 2, tig = lane & 3;
    int qb = qblk * 128 + warp * 32;

    // A fragments (2 M-tiles x 16 rows): a = tf32(-2x)
    unsigned ah[2][4];
#pragma unroll
    for (int mt = 0; mt < 2; ++mt)
#pragma unroll
        for (int i = 0; i < 4; ++i) {
            int row = qb + mt * 16 + (i & 1) * 8 + gid;
            int k = tig + (i >> 1) * 4;
            ah[mt][i] = f2tf(-2.0f * __ldg(x + row * 8 + k));
        }

#pragma unroll 1
    for (int tb = 0; tb < NBLK_SEG; ++tb) {
        int blkg = seg * NBLK_SEG + tb;        // global 64-anchor block id
        int ab = blkg * BLKA;                  // first anchor of block
        float r[2][4];
#pragma unroll 4
        for (int j = 0; j < 8; ++j) {          // 8-anchor MMA groups
            int an = ab + j * 8 + gid;
            uint2  bv = *(const uint2*)(g_pk + an * 8 + tig * 2);
            float2 cn = *(const float2*)(g_nrm + ab + j * 8 + tig * 2);
#pragma unroll
            for (int mt = 0; mt < 2; ++mt) {
                float d[4];
                mma8(d, ah[mt], bv.x, bv.y, cn.x, cn.y);
                if (j == 0) { r[mt][0] = d[0]; r[mt][1] = d[1]; r[mt][2] = d[2]; r[mt][3] = d[3]; }
                else { r[mt][0] = fminf(r[mt][0], d[0]); r[mt][1] = fminf(r[mt][1], d[1]);
                       r[mt][2] = fminf(r[mt][2], d[2]); r[mt][3] = fminf(r[mt][3], d[3]); }
            }
        }
        // per query-slot block-min: combine 2 N-cols, then quad (tig) reduce
#pragma unroll
        for (int s = 0; s < 4; ++s) {
            int mt = s >> 1, rh = s & 1;
            float m = fminf(r[mt][rh * 2], r[mt][rh * 2 + 1]);
            m = fminf(m, __shfl_xor_sync(0xffffffffu, m, 1));
            m = fminf(m, __shfl_xor_sync(0xffffffffu, m, 2));
            if (tig == 0) {
                int q = qb + mt * 16 + rh * 8 + gid;
                g_bmin[(size_t)blkg * NQ + q] = m;   // 8 consecutive q per store wave
            }
        }
    }
}

// ---------------------------------------------------------------------------
// 3) Finalize: complete candidate set (all blocks <= m1+2E), exact fp32
//    rescore, q_sample epilogue. One warp per query.
// ---------------------------------------------------------------------------
__device__ __forceinline__ void score_upd(const float* __restrict__ anchors, int a,
                                          float4 x0, float4 x1, float& ev, int& ei) {
    const float4* ap = (const float4*)(anchors + (size_t)a * DIM);
    float4 a0 = ap[0], a1 = ap[1];
    float nrm = a0.x * a0.x;
    nrm = fmaf(a0.y, a0.y, nrm); nrm = fmaf(a0.z, a0.z, nrm); nrm = fmaf(a0.w, a0.w, nrm);
    nrm = fmaf(a1.x, a1.x, nrm); nrm = fmaf(a1.y, a1.y, nrm); nrm = fmaf(a1.z, a1.z, nrm);
    nrm = fmaf(a1.w, a1.w, nrm);
    float dot = x0.x * a0.x;
    dot = fmaf(x0.y, a0.y, dot); dot = fmaf(x0.z, a0.z, dot); dot = fmaf(x0.w, a0.w, dot);
    dot = fmaf(x1.x, a1.x, dot); dot = fmaf(x1.y, a1.y, dot); dot = fmaf(x1.z, a1.z, dot);
    dot = fmaf(x1.w, a1.w, dot);
    float sv = fmaf(-2.f, dot, nrm);
    if (sv < ev || (sv == ev && a < ei)) { ev = sv; ei = a; }
}

__global__ void __launch_bounds__(256)
finalize_kernel(const float* __restrict__ x, const float* __restrict__ anchors,
                const float* __restrict__ sac, const float* __restrict__ somc,
                const int* __restrict__ t, float* __restrict__ out) {
    __shared__ int s_list[8][CAP];
    __shared__ int s_cnt[8];

    int warp = threadIdx.x >> 5, lane = threadIdx.x & 31;
    int q = blockIdx.x * 8 + warp;

    // each lane covers 4 blocks: lane, lane+32, lane+64, lane+96
    float v[4];
#pragma unroll
    for (int i = 0; i < 4; ++i)
        v[i] = g_bmin[(size_t)(lane + i * 32) * NQ + q];
    float m1 = fminf(fminf(v[0], v[1]), fminf(v[2], v[3]));
#pragma unroll
    for (int off = 16; off >= 1; off >>= 1)
        m1 = fminf(m1, __shfl_xor_sync(0xffffffffu, m1, off));

    const float4* xp = (const float4*)(x + (size_t)q * DIM);
    float4 x0 = xp[0], x1 = xp[1];
    // tf32 coarse error: E <= 2^-10 * S, S = 2*sum_d |x_d|*bmax_d
    float S = fabsf(x0.x) * __uint_as_float(g_bmax[0]);
    S = fmaf(fabsf(x0.y), __uint_as_float(g_bmax[1]), S);
    S = fmaf(fabsf(x0.z), __uint_as_float(g_bmax[2]), S);
    S = fmaf(fabsf(x0.w), __uint_as_float(g_bmax[3]), S);
    S = fmaf(fabsf(x1.x), __uint_as_float(g_bmax[4]), S);
    S = fmaf(fabsf(x1.y), __uint_as_float(g_bmax[5]), S);
    S = fmaf(fabsf(x1.z), __uint_as_float(g_bmax[6]), S);
    S = fmaf(fabsf(x1.w), __uint_as_float(g_bmax[7]), S);
    S *= 2.f;
    float thr = m1 + 2.2e-3f * S + 1e-4f * (1.f + S);   // m1 + 2E + slack

    if (lane == 0) s_cnt[warp] = 0;
    __syncwarp();
#pragma unroll
    for (int i = 0; i < 4; ++i)
        if (v[i] <= thr) {
            int pos = atomicAdd(&s_cnt[warp], 1);
            if (pos < CAP) s_list[warp][pos] = lane + i * 32;
        }
    __syncwarp();
    int cnt = s_cnt[warp];

    float ev = FLT_INF; int ei = 0x7fffffff;
    if (cnt <= CAP) {
        for (int i = 0; i < cnt; ++i) {
            int ab = s_list[warp][i] * BLKA;
            score_upd(anchors, ab + lane, x0, x1, ev, ei);
            score_upd(anchors, ab + 32 + lane, x0, x1, ev, ei);
        }
    } else {
        for (int it = 0; it < MA / 32; ++it)
            score_upd(anchors, it * 32 + lane, x0, x1, ev, ei);
    }
#pragma unroll
    for (int off = 16; off >= 1; off >>= 1) {
        float ov = __shfl_xor_sync(0xffffffffu, ev, off);
        int   oi = __shfl_xor_sync(0xffffffffu, ei, off);
        if (ov < ev || (ov == ev && oi < ei)) { ev = ov; ei = oi; }
    }

    if (lane == 0) {
        int tt = t[q >> 11];                              // N = 2048
        float sa = sac[tt], sb = somc[tt];
        const float4* ap = (const float4*)(anchors + (size_t)ei * DIM);
        float4 a0 = ap[0], a1 = ap[1];
        float4 o0, o1;
        o0.x = sa * x0.x + sb * a0.x; o0.y = sa * x0.y + sb * a0.y;
        o0.z = sa * x0.z + sb * a0.z; o0.w = sa * x0.w + sb * a0.w;
        o1.x = sa * x1.x + sb * a1.x; o1.y = sa * x1.y + sb * a1.y;
        o1.z = sa * x1.z + sb * a1.z; o1.w = sa * x1.w + sb * a1.w;
        float4* op = (float4*)(out + (size_t)q * DIM);
        op[0] = o0; op[1] = o1;
    }
}

// ---------------------------------------------------------------------------
extern "C" void kernel_launch(void* const* d_in, const int* in_sizes, int n_in,
                              void* d_out, int out_size) {
    const float* x    = nullptr;
    const float* anch = nullptr;
    const float* sac  = nullptr;
    const float* somc = nullptr;
    const int*   t    = nullptr;
    for (int i = 0; i < n_in; ++i) {
        int s = in_sizes[i];
        if (s == NQ * DIM && !x)          x    = (const float*)d_in[i];
        else if (s == MA * DIM)           anch = (const float*)d_in[i];
        else if (s == 1000) { if (!sac) sac = (const float*)d_in[i];
                              else      somc = (const float*)d_in[i]; }
        else if (s == 16)                 t    = (const int*)d_in[i];
    }
    prep_kernel<<<MA / 256, 256>>>(anch);
    coarse_kernel<<<(NQ / 128) * SEG, 128>>>(x);
    finalize_kernel<<<NQ / 8, 256>>>(x, anch, sac, somc, t, (float*)d_out);
}

// round 7
// speedup vs baseline: 1.3063x; 1.3063x over previous
#include <cuda_runtime.h>
#include <cuda_fp16.h>

#define NQ   32768
#define MA   8192
#define DIM  8
#define SEG  4
#define APS  (MA/SEG)        // 2048 anchors per segment
#define BLKA 64              // scoring block = 64 anchors
#define NBLK (MA/BLKA)       // 128 blocks total
#define NBLK_SEG (APS/BLKA)  // 32 blocks per segment
#define QPW  64              // queries per warp (4 M-tiles)
#define QPB  128             // queries per block (2 warps)
#define CAP  24
#define FLT_INF __int_as_float(0x7f800000)

// scratch (device globals; no allocation)
__device__ __align__(16) unsigned g_pkh[MA * 4];  // 4 half2 per anchor (k-pairs)
__device__ __align__(16) float    g_nrm[MA];      // exact fp32 ||a||^2
__device__ float    g_bmin[NQ * NBLK];            // q-major: [q][block]
__device__ unsigned g_bmax[DIM];                  // per-dim max |anchor| bits

// fp16 m16n8k16, fp32 accum, B duplicated (k8..15 == k0..7), norms via C
__device__ __forceinline__ void hmma(float d[4],
                                     unsigned a0, unsigned a1, unsigned a2, unsigned a3,
                                     unsigned b, float c0, float c1) {
    asm("mma.sync.aligned.m16n8k16.row.col.f32.f16.f16.f32 "
        "{%0,%1,%2,%3},{%4,%5,%6,%7},{%8,%9},{%10,%11,%12,%13};"
        : "=f"(d[0]), "=f"(d[1]), "=f"(d[2]), "=f"(d[3])
        : "r"(a0), "r"(a1), "r"(a2), "r"(a3), "r"(b), "r"(b),
          "f"(c0), "f"(c1), "f"(c0), "f"(c1));
}

// ---------------------------------------------------------------------------
// 1) Prep: fp16-pack anchors (k-pairs as half2), exact norms, per-dim |a| max
// ---------------------------------------------------------------------------
__global__ void prep_kernel(const float* __restrict__ anchors) {
    int a = blockIdx.x * 256 + threadIdx.x;
    const float4* ap = (const float4*)(anchors + (size_t)a * DIM);
    float4 v0 = ap[0], v1 = ap[1];
    float nrm = v0.x * v0.x;
    nrm = fmaf(v0.y, v0.y, nrm); nrm = fmaf(v0.z, v0.z, nrm); nrm = fmaf(v0.w, v0.w, nrm);
    nrm = fmaf(v1.x, v1.x, nrm); nrm = fmaf(v1.y, v1.y, nrm); nrm = fmaf(v1.z, v1.z, nrm);
    nrm = fmaf(v1.w, v1.w, nrm);
    g_nrm[a] = nrm;
    __half2 p0 = __floats2half2_rn(v0.x, v0.y);
    __half2 p1 = __floats2half2_rn(v0.z, v0.w);
    __half2 p2 = __floats2half2_rn(v1.x, v1.y);
    __half2 p3 = __floats2half2_rn(v1.z, v1.w);
    uint4 pk;
    pk.x = *(unsigned*)&p0; pk.y = *(unsigned*)&p1;
    pk.z = *(unsigned*)&p2; pk.w = *(unsigned*)&p3;
    ((uint4*)g_pkh)[a] = pk;

    unsigned um[8] = { __float_as_uint(fabsf(v0.x)), __float_as_uint(fabsf(v0.y)),
                       __float_as_uint(fabsf(v0.z)), __float_as_uint(fabsf(v0.w)),
                       __float_as_uint(fabsf(v1.x)), __float_as_uint(fabsf(v1.y)),
                       __float_as_uint(fabsf(v1.z)), __float_as_uint(fabsf(v1.w)) };
    __shared__ unsigned sm[8];
    if (threadIdx.x < 8) sm[threadIdx.x] = 0;
    __syncthreads();
#pragma unroll
    for (int d = 0; d < 8; ++d) um[d] = __reduce_max_sync(0xffffffffu, um[d]);
    if ((threadIdx.x & 31) == 0)
#pragma unroll
        for (int d = 0; d < 8; ++d) atomicMax(&sm[d], um[d]);
    __syncthreads();
    if (threadIdx.x < 8) atomicMax(&g_bmax[threadIdx.x], sm[threadIdx.x]);
}

// ---------------------------------------------------------------------------
// 2) Coarse: fp16 MMA (A = exact hi/lo split of -2x, B = fp16(anchor), norms
//    via fp32 C). Warp = 64 queries x 1 segment (2048 anchors). Block-mins
//    buffered in smem, flushed q-major coalesced.
// ---------------------------------------------------------------------------
__global__ void __launch_bounds__(64)
coarse_kernel(const float* __restrict__ x) {
    __shared__ float sm[QPB * 33];   // [q_local][33] padded (bank-conflict-free)

    int seg  = blockIdx.x & (SEG - 1);
    int qblk = blockIdx.x >> 2;
    int warp = threadIdx.x >> 5, lane = threadIdx.x & 31;
    int gid = lane >> 2, tig = lane & 3;
    int qb = qblk * QPB + warp * QPW;

    // A fragments: 4 M-tiles, a = -2x split exactly into fp16 hi (k0..7) + lo (k8..15)
    unsigned afr[4][4];
#pragma unroll
    for (int mt = 0; mt < 4; ++mt)
#pragma unroll
        for (int rh = 0; rh < 2; ++rh) {
            int row = qb + mt * 16 + rh * 8 + gid;
            float2 xv = *(const float2*)(x + row * 8 + tig * 2);
            float v0 = -2.f * xv.x, v1 = -2.f * xv.y;
            __half h0 = __float2half_rn(v0), h1 = __float2half_rn(v1);
            float l0 = v0 - __half2float(h0), l1 = v1 - __half2float(h1);
            __half2 hh = __halves2half2(h0, h1);
            __half2 ll = __floats2half2_rn(l0, l1);
            afr[mt][rh]     = *(unsigned*)&hh;
            afr[mt][2 + rh] = *(unsigned*)&ll;
        }

#pragma unroll 1
    for (int tb = 0; tb < NBLK_SEG; ++tb) {
        int ab = (seg * NBLK_SEG + tb) * BLKA;    // first anchor of block
        float r[4][4];
#pragma unroll
        for (int j = 0; j < 8; ++j) {             // 8-anchor MMA groups
            unsigned bb = g_pkh[(ab + j * 8 + gid) * 4 + tig];
            float2 cn = *(const float2*)(g_nrm + ab + j * 8 + tig * 2);
#pragma unroll
            for (int mt = 0; mt < 4; ++mt) {
                float d[4];
                hmma(d, afr[mt][0], afr[mt][1], afr[mt][2], afr[mt][3], bb, cn.x, cn.y);
                if (j == 0) { r[mt][0] = d[0]; r[mt][1] = d[1]; r[mt][2] = d[2]; r[mt][3] = d[3]; }
                else { r[mt][0] = fminf(r[mt][0], d[0]); r[mt][1] = fminf(r[mt][1], d[1]);
                       r[mt][2] = fminf(r[mt][2], d[2]); r[mt][3] = fminf(r[mt][3], d[3]); }
            }
        }
        // per query-slot min: 2 N-cols combine, quad (tig) shfl reduce, stash in smem
#pragma unroll
        for (int mt = 0; mt < 4; ++mt)
#pragma unroll
            for (int rh = 0; rh < 2; ++rh) {
                float m = fminf(r[mt][rh * 2], r[mt][rh * 2 + 1]);
                m = fminf(m, __shfl_xor_sync(0xffffffffu, m, 1));
                m = fminf(m, __shfl_xor_sync(0xffffffffu, m, 2));
                if (tig == 0) {
                    int ql = warp * QPW + mt * 16 + rh * 8 + gid;
                    sm[ql * 33 + tb] = m;
                }
            }
    }
    __syncwarp();
    // flush q-major, coalesced 128B stores
#pragma unroll 4
    for (int i = 0; i < QPW; ++i) {
        int ql = warp * QPW + i;
        g_bmin[(size_t)(qblk * QPB + ql) * NBLK + seg * NBLK_SEG + lane] = sm[ql * 33 + lane];
    }
}

// ---------------------------------------------------------------------------
// 3) Finalize: complete candidate set (all blocks <= m1+2E), exact fp32
//    rescore, q_sample epilogue. One warp per query.
// ---------------------------------------------------------------------------
__device__ __forceinline__ void score_upd(const float* __restrict__ anchors, int a,
                                          float4 x0, float4 x1, float& ev, int& ei) {
    const float4* ap = (const float4*)(anchors + (size_t)a * DIM);
    float4 a0 = ap[0], a1 = ap[1];
    float nrm = a0.x * a0.x;
    nrm = fmaf(a0.y, a0.y, nrm); nrm = fmaf(a0.z, a0.z, nrm); nrm = fmaf(a0.w, a0.w, nrm);
    nrm = fmaf(a1.x, a1.x, nrm); nrm = fmaf(a1.y, a1.y, nrm); nrm = fmaf(a1.z, a1.z, nrm);
    nrm = fmaf(a1.w, a1.w, nrm);
    float dot = x0.x * a0.x;
    dot = fmaf(x0.y, a0.y, dot); dot = fmaf(x0.z, a0.z, dot); dot = fmaf(x0.w, a0.w, dot);
    dot = fmaf(x1.x, a1.x, dot); dot = fmaf(x1.y, a1.y, dot); dot = fmaf(x1.z, a1.z, dot);
    dot = fmaf(x1.w, a1.w, dot);
    float sv = fmaf(-2.f, dot, nrm);
    if (sv < ev || (sv == ev && a < ei)) { ev = sv; ei = a; }
}

__global__ void __launch_bounds__(256)
finalize_kernel(const float* __restrict__ x, const float* __restrict__ anchors,
                const float* __restrict__ sac, const float* __restrict__ somc,
                const int* __restrict__ t, float* __restrict__ out) {
    __shared__ int s_list[8][CAP];
    __shared__ int s_cnt[8];

    int warp = threadIdx.x >> 5, lane = threadIdx.x & 31;
    int q = blockIdx.x * 8 + warp;

    // coalesced q-major reads: lane covers blocks lane, lane+32, lane+64, lane+96
    float v[4];
#pragma unroll
    for (int i = 0; i < 4; ++i)
        v[i] = g_bmin[(size_t)q * NBLK + lane + i * 32];
    float m1 = fminf(fminf(v[0], v[1]), fminf(v[2], v[3]));
#pragma unroll
    for (int off = 16; off >= 1; off >>= 1)
        m1 = fminf(m1, __shfl_xor_sync(0xffffffffu, m1, off));

    const float4* xp = (const float4*)(x + (size_t)q * DIM);
    float4 x0 = xp[0], x1 = xp[1];
    // fp16-B coarse error: E <= 2^-11 * S, S = 2*sum_d |x_d|*bmax_d
    float S = fabsf(x0.x) * __uint_as_float(g_bmax[0]);
    S = fmaf(fabsf(x0.y), __uint_as_float(g_bmax[1]), S);
    S = fmaf(fabsf(x0.z), __uint_as_float(g_bmax[2]), S);
    S = fmaf(fabsf(x0.w), __uint_as_float(g_bmax[3]), S);
    S = fmaf(fabsf(x1.x), __uint_as_float(g_bmax[4]), S);
    S = fmaf(fabsf(x1.y), __uint_as_float(g_bmax[5]), S);
    S = fmaf(fabsf(x1.z), __uint_as_float(g_bmax[6]), S);
    S = fmaf(fabsf(x1.w), __uint_as_float(g_bmax[7]), S);
    S *= 2.f;
    float thr = m1 + 1.0e-3f * S + 1e-4f * (1.f + S);   // m1 + 2E + slack

    if (lane == 0) s_cnt[warp] = 0;
    __syncwarp();
#pragma unroll
    for (int i = 0; i < 4; ++i)
        if (v[i] <= thr) {
            int pos = atomicAdd(&s_cnt[warp], 1);
            if (pos < CAP) s_list[warp][pos] = lane + i * 32;
        }
    __syncwarp();
    int cnt = s_cnt[warp];

    float ev = FLT_INF; int ei = 0x7fffffff;
    if (cnt <= CAP) {
        for (int i = 0; i < cnt; ++i) {
            int ab = s_list[warp][i] * BLKA;
            score_upd(anchors, ab + lane, x0, x1, ev, ei);
            score_upd(anchors, ab + 32 + lane, x0, x1, ev, ei);
        }
    } else {
        for (int it = 0; it < MA / 32; ++it)
            score_upd(anchors, it * 32 + lane, x0, x1, ev, ei);
    }
#pragma unroll
    for (int off = 16; off >= 1; off >>= 1) {
        float ov = __shfl_xor_sync(0xffffffffu, ev, off);
        int   oi = __shfl_xor_sync(0xffffffffu, ei, off);
        if (ov < ev || (ov == ev && oi < ei)) { ev = ov; ei = oi; }
    }

    if (lane == 0) {
        int tt = t[q >> 11];                              // N = 2048
        float sa = sac[tt], sb = somc[tt];
        const float4* ap = (const float4*)(anchors + (size_t)ei * DIM);
        float4 a0 = ap[0], a1 = ap[1];
        float4 o0, o1;
        o0.x = sa * x0.x + sb * a0.x; o0.y = sa * x0.y + sb * a0.y;
        o0.z = sa * x0.z + sb * a0.z; o0.w = sa * x0.w + sb * a0.w;
        o1.x = sa * x1.x + sb * a1.x; o1.y = sa * x1.y + sb * a1.y;
        o1.z = sa * x1.z + sb * a1.z; o1.w = sa * x1.w + sb * a1.w;
        float4* op = (float4*)(out + (size_t)q * DIM);
        op[0] = o0; op[1] = o1;
    }
}

// ---------------------------------------------------------------------------
extern "C" void kernel_launch(void* const* d_in, const int* in_sizes, int n_in,
                              void* d_out, int out_size) {
    const float* x    = nullptr;
    const float* anch = nullptr;
    const float* sac  = nullptr;
    const float* somc = nullptr;
    const int*   t    = nullptr;
    for (int i = 0; i < n_in; ++i) {
        int s = in_sizes[i];
        if (s == NQ * DIM && !x)          x    = (const float*)d_in[i];
        else if (s == MA * DIM)           anch = (const float*)d_in[i];
        else if (s == 1000) { if (!sac) sac = (const float*)d_in[i];
                              else      somc = (const float*)d_in[i]; }
        else if (s == 16)                 t    = (const int*)d_in[i];
    }
    prep_kernel<<<MA / 256, 256>>>(anch);
    coarse_kernel<<<(NQ / QPB) * SEG, 64>>>(x);
    finalize_kernel<<<NQ / 8, 256>>>(x, anch, sac, somc, t, (float*)d_out);
}